// round 3
// baseline (speedup 1.0000x reference)
#include <cuda_runtime.h>

// GaussianBlur2D: depthwise 11x11 Gaussian blur, reflect padding.
// x: (16, 64, 512, 512) fp32, sigma: (1,) fp32.
//
// Separable, horizontal-first, ZERO shared memory / ZERO barriers:
//   - horizontal 11-tap at load time from 3x LDG.128 + 2x LDG.32 per row
//   - 14-deep register window of h-blurred rows; vertical 11-tap in registers
//   - results written with STG.128
// g2d[i][j] = (h[i]/S)*(h[j]/S) with S = sum(h)  == reference's 2D kernel.

#define KS    11
#define IMG   512
#define NT    128      // threads per block; NT*4 == IMG (one full row per block)
#define RPT   4        // output rows produced per loop iteration
#define STRIP 128      // output rows per block

__device__ float g_w[KS];

__global__ void compute_weights_kernel(const float* __restrict__ sigma) {
    if (threadIdx.x == 0) {
        float s = fabsf(sigma[0]) + 1e-6f;
        float inv = 1.0f / (2.0f * s * s);
        float h[KS];
        float sum = 0.0f;
        #pragma unroll
        for (int j = 0; j < KS; j++) {
            float r = (float)j - (float)(KS - 1) * 0.5f;
            h[j] = __expf(-r * r * inv);
            sum += h[j];
        }
        float rs = 1.0f / sum;
        #pragma unroll
        for (int j = 0; j < KS; j++) g_w[j] = h[j] * rs;
    }
}

__device__ __forceinline__ int refl(int i) {
    i = (i < 0) ? -i : i;
    return (i >= IMG) ? (2 * IMG - 2 - i) : i;
}

// Horizontal 11-tap blur producing columns x..x+3 of one row.
// Needs input columns x-5..x+8 (14 values): 2 reflected scalars + 3 aligned float4.
__device__ __forceinline__ float4 hblur_row(const float* __restrict__ row,
                                            int x, const float* __restrict__ w) {
    float v[14];
    v[0]  = row[refl(x - 5)];
    v[13] = row[refl(x + 8)];

    float4 m1, m3;
    if (x != 0) {
        m1 = *(const float4*)(row + x - 4);             // cols x-4..x-1
    } else {                                            // cols -4..-1 -> 4..1
        m1 = make_float4(row[4], row[3], row[2], row[1]);
    }
    const float4 m2 = *(const float4*)(row + x);        // cols x..x+3
    if (x != IMG - 4) {
        m3 = *(const float4*)(row + x + 4);             // cols x+4..x+7
    } else {                                            // cols 512..515 -> 510..507
        m3 = make_float4(row[510], row[509], row[508], row[507]);
    }
    v[1] = m1.x; v[2]  = m1.y; v[3]  = m1.z; v[4]  = m1.w;
    v[5] = m2.x; v[6]  = m2.y; v[7]  = m2.z; v[8]  = m2.w;
    v[9] = m3.x; v[10] = m3.y; v[11] = m3.z; v[12] = m3.w;

    float o0 = 0.f, o1 = 0.f, o2 = 0.f, o3 = 0.f;
    #pragma unroll
    for (int j = 0; j < KS; j++) {
        const float wj = w[j];
        o0 = fmaf(wj, v[j],     o0);
        o1 = fmaf(wj, v[j + 1], o1);
        o2 = fmaf(wj, v[j + 2], o2);
        o3 = fmaf(wj, v[j + 3], o3);
    }
    return make_float4(o0, o1, o2, o3);
}

__global__ __launch_bounds__(NT, 4)
void gaussian_blur_kernel(const float* __restrict__ in, float* __restrict__ out) {
    const int t = threadIdx.x;
    const int x = t << 2;                       // this thread owns columns x..x+3
    const int plane = blockIdx.x >> 2;
    const int y0 = (blockIdx.x & 3) * STRIP;
    const float* __restrict__ img  = in  + (size_t)plane * (IMG * IMG);
    float*       __restrict__ oimg = out + (size_t)plane * (IMG * IMG);

    float w[KS];
    #pragma unroll
    for (int i = 0; i < KS; i++) w[i] = g_w[i];

    // win[k] = hblur of input row (ybase + k - 5), k = 0..13 (rows for outputs ybase..ybase+3)
    float4 win[14];
    #pragma unroll
    for (int k = 0; k < 14; k++)
        win[k] = hblur_row(img + (size_t)refl(y0 + k - 5) * IMG, x, w);

    for (int yb = 0; yb < STRIP; yb += RPT) {
        const int y = y0 + yb;

        // Fetch + h-blur the next RPT rows (y+9 .. y+12); overlaps the vblur FMAs below.
        float4 nw[RPT];
        if (yb + RPT < STRIP) {
            #pragma unroll
            for (int r = 0; r < RPT; r++)
                nw[r] = hblur_row(img + (size_t)refl(y + 9 + r) * IMG, x, w);
        }

        // Vertical 11-tap from the register window -> 4 output rows.
        #pragma unroll
        for (int r = 0; r < RPT; r++) {
            float ax = 0.f, ay = 0.f, az = 0.f, aw = 0.f;
            #pragma unroll
            for (int i = 0; i < KS; i++) {
                const float  wi = w[i];
                const float4 v  = win[r + i];
                ax = fmaf(wi, v.x, ax);
                ay = fmaf(wi, v.y, ay);
                az = fmaf(wi, v.z, az);
                aw = fmaf(wi, v.w, aw);
            }
            *(float4*)(oimg + (size_t)(y + r) * IMG + x) = make_float4(ax, ay, az, aw);
        }

        // Slide the window down by RPT rows.
        #pragma unroll
        for (int k = 0; k < 14 - RPT; k++) win[k] = win[k + RPT];
        #pragma unroll
        for (int r = 0; r < RPT; r++)      win[10 + r] = nw[r];
    }
}

extern "C" void kernel_launch(void* const* d_in, const int* in_sizes, int n_in,
                              void* d_out, int out_size) {
    const float* x     = (const float*)d_in[0];
    const float* sigma = (const float*)d_in[1];
    float*       out   = (float*)d_out;

    const int n_img = in_sizes[0] / (IMG * IMG);   // B*C planes

    compute_weights_kernel<<<1, 32>>>(sigma);

    const int strips = IMG / STRIP;                // 4
    gaussian_blur_kernel<<<n_img * strips, NT>>>(x, out);
}